// round 3
// baseline (speedup 1.0000x reference)
#include <cuda_runtime.h>
#include <math.h>

#define NTHREADS 224

// ---- packed f32x2 helpers (sm_103a FFMA2 path; ptxas won't auto-fuse) ----
__device__ __forceinline__ unsigned long long pack2(float x, float y) {
    unsigned long long r;
    asm("mov.b64 %0, {%1, %2};" : "=l"(r) : "f"(x), "f"(y));
    return r;
}
__device__ __forceinline__ unsigned long long fma2(unsigned long long a,
                                                   unsigned long long b,
                                                   unsigned long long c) {
    unsigned long long d;
    asm("fma.rn.f32x2 %0, %1, %2, %3;" : "=l"(d) : "l"(a), "l"(b), "l"(c));
    return d;
}
__device__ __forceinline__ float2 unpack2(unsigned long long v) {
    float x, y;
    asm("mov.b64 {%0, %1}, %2;" : "=f"(x), "=f"(y) : "l"(v));
    return make_float2(x, y);
}

// One block per image. 224 threads = 7 full warps; threads 0..195 own one
// 2x2 patch each. qfeat is never materialized: each patch folds probs@Z
// directly into the w_cls dot product; a single 3-way block reduction
// (sum, sumsq, qdot) feeds the fused classical MLP + sigmoid on thread 0.
extern "C" __global__ void __launch_bounds__(NTHREADS)
fraud_kernel(const float* __restrict__ x,
             const float* __restrict__ w_in,  const float* __restrict__ b_in,
             const float* __restrict__ scale_in, const float* __restrict__ shift_in,
             const float* __restrict__ Wc,    const float* __restrict__ bc,
             const float* __restrict__ scalec, const float* __restrict__ shiftc,
             const float* __restrict__ w_out, const float* __restrict__ b_out,
             const float* __restrict__ U_re,  const float* __restrict__ U_im,
             const float* __restrict__ w_cls, const float* __restrict__ b_cls,
             float* __restrict__ out, int Lc)
{
    __shared__ float xs[784];          // the image
    __shared__ ulonglong2 Us[128];     // U as interleaved (re,im) f32 pairs, [k][I/2]
    __shared__ float wcs[788];         // classifier weights (785 used)
    __shared__ float redS[7], redQ[7], redC[7];

    const int t = threadIdx.x;
    const int b = blockIdx.x;
    const float* xb = x + b * 784;

    // cooperative loads + local sums for mean/std
    float lsum = 0.f, lsq = 0.f;
    #pragma unroll
    for (int i = t; i < 784; i += NTHREADS) {
        float v = xb[i];
        xs[i] = v;
        lsum += v;
        lsq  += v * v;
    }
    unsigned long long* Us1 = reinterpret_cast<unsigned long long*>(Us);
    for (int i = t; i < 256; i += NTHREADS)
        Us1[i] = pack2(U_re[i], U_im[i]);
    for (int i = t; i < 785; i += NTHREADS)
        wcs[i] = w_cls[i];
    __syncthreads();

    float cacc = 0.f;
    if (t < 196) {
        // patch pixels: [x[r,c], x[r,c+1], x[r+1,c], x[r+1,c+1]]
        const int pr14 = t / 14, pc14 = t % 14;
        const float* px = xs + pr14 * 56 + pc14 * 2;
        const float p0 = px[0], p1 = px[1], p2 = px[28], p3 = px[29];

        float s0, c0, s1, c1, s2, c2, s3, c3;
        __sincosf(0.5f * p0, &s0, &c0);
        __sincosf(0.5f * p1, &s1, &c1);
        __sincosf(0.5f * p2, &s2, &c2);
        __sincosf(0.5f * p3, &s3, &c3);

        // product state psi[8i+4j+2k+l] = a0_i a1_j a2_k a3_l, stored splatted
        float a01[4] = {c0 * c1, c0 * s1, s0 * c1, s0 * s1};
        float a23[4] = {c2 * c3, c2 * s3, s2 * c3, s2 * s3};
        unsigned long long psiP[16];
        #pragma unroll
        for (int i = 0; i < 4; i++)
            #pragma unroll
            for (int j = 0; j < 4; j++) {
                float v = a01[i] * a23[j];
                psiP[i * 4 + j] = pack2(v, v);
            }

        // probs_k = |sum_I U[k,I] psi_I|^2  via packed (re,im) FFMA2
        float prob[16];
        #pragma unroll
        for (int k = 0; k < 16; k++) {
            unsigned long long acc0 = 0ull, acc1 = 0ull;
            #pragma unroll
            for (int h = 0; h < 8; h += 2) {
                ulonglong2 ua = Us[k * 8 + h];
                ulonglong2 ub = Us[k * 8 + h + 1];
                acc0 = fma2(ua.x, psiP[2 * h + 0], acc0);
                acc1 = fma2(ua.y, psiP[2 * h + 1], acc1);
                acc0 = fma2(ub.x, psiP[2 * h + 2], acc0);
                acc1 = fma2(ub.y, psiP[2 * h + 3], acc1);
            }
            float2 r0 = unpack2(acc0);
            float2 r1 = unpack2(acc1);
            float re = r0.x + r1.x;
            float im = r0.y + r1.y;
            prob[k] = re * re + im * im;
        }

        // probs @ Z folded with w_cls: qfeat_w = T - 2*sum_{k: bit(3-w)} p_k
        float T = 0.f, t0 = 0.f, t1 = 0.f, t2 = 0.f, t3 = 0.f;
        #pragma unroll
        for (int k = 0; k < 16; k++) {
            T += prob[k];
            if (k & 8) t0 += prob[k];
            if (k & 4) t1 += prob[k];
            if (k & 2) t2 += prob[k];
            if (k & 1) t3 += prob[k];
        }
        const float* wc = wcs + 1 + 4 * t;
        cacc = (T - 2.f * t0) * wc[0] + (T - 2.f * t1) * wc[1]
             + (T - 2.f * t2) * wc[2] + (T - 2.f * t3) * wc[3];
    }

    // 3-way block reduction (sum, sumsq, quantum dot)
    #pragma unroll
    for (int off = 16; off > 0; off >>= 1) {
        lsum += __shfl_down_sync(0xffffffffu, lsum, off);
        lsq  += __shfl_down_sync(0xffffffffu, lsq,  off);
        cacc += __shfl_down_sync(0xffffffffu, cacc, off);
    }
    const int wid = t >> 5;
    if ((t & 31) == 0) { redS[wid] = lsum; redQ[wid] = lsq; redC[wid] = cacc; }
    __syncthreads();

    if (t == 0) {
        float S = 0.f, Q = 0.f, C = 0.f;
        #pragma unroll
        for (int i = 0; i < 7; i++) { S += redS[i]; Q += redQ[i]; C += redC[i]; }
        float mean = S * (1.f / 784.f);
        float var  = (Q - S * S * (1.f / 784.f)) * (1.f / 783.f);  // ddof=1
        float sd   = sqrtf(fmaxf(var, 0.f));
        float h0 = tanhf(mean * w_in[0] + sd * w_in[1] + b_in[0]) * scale_in[0] + shift_in[0];
        float h1 = tanhf(mean * w_in[2] + sd * w_in[3] + b_in[1]) * scale_in[1] + shift_in[1];
        for (int l = 0; l < Lc; l++) {
            float n0 = tanhf(h0 * Wc[l*4+0] + h1 * Wc[l*4+1] + bc[l*2+0]) * scalec[l*2+0] + shiftc[l*2+0];
            float n1 = tanhf(h0 * Wc[l*4+2] + h1 * Wc[l*4+3] + bc[l*2+1]) * scalec[l*2+1] + shiftc[l*2+1];
            h0 = n0; h1 = n1;
        }
        float cls = h0 * w_out[0] + h1 * w_out[1] + b_out[0];
        float logit = b_cls[0] + cls * wcs[0] + C;
        out[b] = 1.f / (1.f + __expf(-logit));
    }
}

extern "C" void kernel_launch(void* const* d_in, const int* in_sizes, int n_in,
                              void* d_out, int out_size)
{
    const float* x        = (const float*)d_in[0];
    const float* w_in     = (const float*)d_in[1];
    const float* b_in     = (const float*)d_in[2];
    const float* scale_in = (const float*)d_in[3];
    const float* shift_in = (const float*)d_in[4];
    const float* Wc       = (const float*)d_in[5];
    const float* bc       = (const float*)d_in[6];
    const float* scalec   = (const float*)d_in[7];
    const float* shiftc   = (const float*)d_in[8];
    const float* w_out    = (const float*)d_in[9];
    const float* b_out    = (const float*)d_in[10];
    const float* U_re     = (const float*)d_in[11];
    const float* U_im     = (const float*)d_in[12];
    const float* w_cls    = (const float*)d_in[13];
    const float* b_cls    = (const float*)d_in[14];
    float* out = (float*)d_out;

    const int B  = in_sizes[0] / 784;   // (B,1,28,28)
    const int Lc = in_sizes[5] / 4;     // (L,2,2)

    fraud_kernel<<<B, NTHREADS>>>(x, w_in, b_in, scale_in, shift_in,
                                  Wc, bc, scalec, shiftc, w_out, b_out,
                                  U_re, U_im, w_cls, b_cls, out, Lc);
}

// round 4
// speedup vs baseline: 1.7389x; 1.7389x over previous
#include <cuda_runtime.h>
#include <math.h>

typedef unsigned long long u64;

// ---- packed f32x2 helpers (sm_103a; ptxas won't auto-fuse) ----
__device__ __forceinline__ u64 pack2(float x, float y) {
    u64 r; asm("mov.b64 %0, {%1, %2};" : "=l"(r) : "f"(x), "f"(y)); return r;
}
__device__ __forceinline__ u64 fma2(u64 a, u64 b, u64 c) {
    u64 d; asm("fma.rn.f32x2 %0, %1, %2, %3;" : "=l"(d) : "l"(a), "l"(b), "l"(c)); return d;
}
__device__ __forceinline__ u64 mul2(u64 a, u64 b) {
    u64 d; asm("mul.rn.f32x2 %0, %1, %2;" : "=l"(d) : "l"(a), "l"(b)); return d;
}
__device__ __forceinline__ float2 unpack2(u64 v) {
    float x, y; asm("mov.b64 {%0, %1}, %2;" : "=f"(x), "=f"(y) : "l"(v)); return make_float2(x, y);
}

#define MAXB 8192
#define TILE 128

// A_p folded matrices, pair layout: g_A2[p*128 + j*8 + r] = (A_p[r][j], A_p[r+8][j])
__device__ __align__(16) float2 g_A2[196 * 128];
// per-(row-group, image) partials: [0:14*B) sum, [14B:28B) sumsq, [28B:42B) qdot
__device__ float g_part[3 * 14 * MAXB];

// ---------------------------------------------------------------------------
// Kernel 1: fold U and w_cls into 196 symmetric 16x16 quadratic-form matrices.
// A_p[i][j] = sum_k g_{p,k} (Ur[k,i]Ur[k,j] + Ui[k,i]Ui[k,j]),
// g_{p,k} = sum_w Z[k,w] * w_cls[1 + 4p + w].
// ---------------------------------------------------------------------------
__global__ void __launch_bounds__(128) precomp_A(const float* __restrict__ U_re,
                                                 const float* __restrict__ U_im,
                                                 const float* __restrict__ w_cls)
{
    __shared__ float urs[256], uis[256];
    const int t = threadIdx.x, p = blockIdx.x;
    for (int i = t; i < 256; i += 128) { urs[i] = U_re[i]; uis[i] = U_im[i]; }
    __syncthreads();

    const int j = t >> 3, r = t & 7;
    const float wc0 = w_cls[1 + 4 * p + 0];
    const float wc1 = w_cls[1 + 4 * p + 1];
    const float wc2 = w_cls[1 + 4 * p + 2];
    const float wc3 = w_cls[1 + 4 * p + 3];
    const float tot = wc0 + wc1 + wc2 + wc3;

    float lo = 0.f, hi = 0.f;
    #pragma unroll
    for (int k = 0; k < 16; k++) {
        float g = tot - 2.f * (((k & 8) ? wc0 : 0.f) + ((k & 4) ? wc1 : 0.f) +
                               ((k & 2) ? wc2 : 0.f) + ((k & 1) ? wc3 : 0.f));
        float urj = urs[k * 16 + j], uij = uis[k * 16 + j];
        lo += g * (urs[k * 16 + r]     * urj + uis[k * 16 + r]     * uij);
        hi += g * (urs[k * 16 + r + 8] * urj + uis[k * 16 + r + 8] * uij);
    }
    g_A2[p * 128 + j * 8 + r] = make_float2(lo, hi);
}

// ---------------------------------------------------------------------------
// Kernel 2: quantum branch as quadratic forms. Block = (128-image tile) x
// (patch-row group rg). Stages rows 2rg,2rg+1 of 128 images + the 14 A
// matrices into smem; each thread computes 14 quadratic forms for its image
// and the mean/std partial sums, then writes deterministic partials.
// ---------------------------------------------------------------------------
__global__ void __launch_bounds__(TILE) quantum_kernel(const float* __restrict__ x, int B)
{
    __shared__ float xs[TILE * 57];               // 57-pad: conflict-free per-thread rows
    __shared__ __align__(16) float2 As[14 * 128]; // 14 A matrices for this row group

    const int t  = threadIdx.x;
    const int b0 = blockIdx.x * TILE;
    const int rg = blockIdx.y;                    // 0..13

    const float2* gA = g_A2 + rg * 14 * 128;
    for (int i = t; i < 14 * 128; i += TILE) As[i] = gA[i];

    const int nimg = min(TILE, B - b0);
    const float* xb = x + (size_t)b0 * 784 + rg * 56;   // rows 2rg,2rg+1 are contiguous
    for (int i = t; i < nimg * 56; i += TILE) {
        int img = i / 56, c = i - img * 56;
        xs[img * 57 + c] = xb[(size_t)img * 784 + c];
    }
    __syncthreads();
    if (t >= nimg) return;                        // no further block syncs below

    float S = 0.f, Q = 0.f, C = 0.f;
    const float* xt = xs + t * 57;

    #pragma unroll 1
    for (int pc = 0; pc < 14; pc++) {
        const float p0 = xt[2 * pc], p1 = xt[2 * pc + 1];
        const float p2 = xt[28 + 2 * pc], p3 = xt[29 + 2 * pc];
        S += (p0 + p1) + (p2 + p3);
        Q += p0 * p0 + p1 * p1 + p2 * p2 + p3 * p3;

        float s0, c0, s1, c1, s2, c2, s3, c3;
        __sincosf(0.5f * p0, &s0, &c0);
        __sincosf(0.5f * p1, &s1, &c1);
        __sincosf(0.5f * p2, &s2, &c2);
        __sincosf(0.5f * p3, &s3, &c3);

        const float a01[4] = {c0 * c1, c0 * s1, s0 * c1, s0 * s1};
        const float a23[4] = {c2 * c3, c2 * s3, s2 * c3, s2 * s3};

        // y = A psi with paired rows (r, r+8): acc[r] = (y_r, y_{r+8})
        u64 acc[8] = {0ull, 0ull, 0ull, 0ull, 0ull, 0ull, 0ull, 0ull};
        const ulonglong2* Arow = (const ulonglong2*)(As + pc * 128);
        #pragma unroll
        for (int j = 0; j < 16; j++) {
            float v = a01[j >> 2] * a23[j & 3];   // psi_j
            u64 vs = pack2(v, v);
            #pragma unroll
            for (int h = 0; h < 4; h++) {
                ulonglong2 e = Arow[j * 4 + h];   // pairs r=2h, r=2h+1 (broadcast LDS.128)
                acc[2 * h]     = fma2(e.x, vs, acc[2 * h]);
                acc[2 * h + 1] = fma2(e.y, vs, acc[2 * h + 1]);
            }
        }

        // q = psi . y  via pairs (psi_r, psi_{r+8})
        const u64 a01p0 = pack2(a01[0], a01[2]);  // (a01[b], a01[b+2]) for b=0
        const u64 a01p1 = pack2(a01[1], a01[3]);  // b=1
        u64 a23s[4];
        #pragma unroll
        for (int c = 0; c < 4; c++) a23s[c] = pack2(a23[c], a23[c]);
        u64 q2 = 0ull;
        #pragma unroll
        for (int r2 = 0; r2 < 8; r2++) {
            u64 pp = mul2((r2 < 4) ? a01p0 : a01p1, a23s[r2 & 3]);
            q2 = fma2(acc[r2], pp, q2);
        }
        float2 qq = unpack2(q2);
        C += qq.x + qq.y;
    }

    const int b = b0 + t;
    g_part[rg * B + b]            = S;
    g_part[(14 + rg) * B + b]     = Q;
    g_part[(28 + rg) * B + b]     = C;
}

// ---------------------------------------------------------------------------
// Kernel 3: sum partials, classical MLP, fuse, sigmoid.
// ---------------------------------------------------------------------------
__global__ void final_kernel(const float* __restrict__ w_in,  const float* __restrict__ b_in,
                             const float* __restrict__ scale_in, const float* __restrict__ shift_in,
                             const float* __restrict__ Wc,    const float* __restrict__ bc,
                             const float* __restrict__ scalec, const float* __restrict__ shiftc,
                             const float* __restrict__ w_out, const float* __restrict__ b_out,
                             const float* __restrict__ w_cls, const float* __restrict__ b_cls,
                             float* __restrict__ out, int B, int Lc)
{
    const int b = blockIdx.x * 256 + threadIdx.x;
    if (b >= B) return;
    float S = 0.f, Q = 0.f, C = 0.f;
    #pragma unroll
    for (int rg = 0; rg < 14; rg++) {
        S += g_part[rg * B + b];
        Q += g_part[(14 + rg) * B + b];
        C += g_part[(28 + rg) * B + b];
    }
    float mean = S * (1.f / 784.f);
    float var  = (Q - S * S * (1.f / 784.f)) * (1.f / 783.f);   // ddof=1
    float sd   = sqrtf(fmaxf(var, 0.f));
    float h0 = tanhf(mean * w_in[0] + sd * w_in[1] + b_in[0]) * scale_in[0] + shift_in[0];
    float h1 = tanhf(mean * w_in[2] + sd * w_in[3] + b_in[1]) * scale_in[1] + shift_in[1];
    for (int l = 0; l < Lc; l++) {
        float n0 = tanhf(h0 * Wc[l*4+0] + h1 * Wc[l*4+1] + bc[l*2+0]) * scalec[l*2+0] + shiftc[l*2+0];
        float n1 = tanhf(h0 * Wc[l*4+2] + h1 * Wc[l*4+3] + bc[l*2+1]) * scalec[l*2+1] + shiftc[l*2+1];
        h0 = n0; h1 = n1;
    }
    float cls   = h0 * w_out[0] + h1 * w_out[1] + b_out[0];
    float logit = b_cls[0] + cls * w_cls[0] + C;
    out[b] = 1.f / (1.f + __expf(-logit));
}

extern "C" void kernel_launch(void* const* d_in, const int* in_sizes, int n_in,
                              void* d_out, int out_size)
{
    const float* x        = (const float*)d_in[0];
    const float* w_in     = (const float*)d_in[1];
    const float* b_in     = (const float*)d_in[2];
    const float* scale_in = (const float*)d_in[3];
    const float* shift_in = (const float*)d_in[4];
    const float* Wc       = (const float*)d_in[5];
    const float* bc       = (const float*)d_in[6];
    const float* scalec   = (const float*)d_in[7];
    const float* shiftc   = (const float*)d_in[8];
    const float* w_out    = (const float*)d_in[9];
    const float* b_out    = (const float*)d_in[10];
    const float* U_re     = (const float*)d_in[11];
    const float* U_im     = (const float*)d_in[12];
    const float* w_cls    = (const float*)d_in[13];
    const float* b_cls    = (const float*)d_in[14];
    float* out = (float*)d_out;

    const int B  = in_sizes[0] / 784;   // (B,1,28,28)
    const int Lc = in_sizes[5] / 4;     // (L,2,2)

    precomp_A<<<196, 128>>>(U_re, U_im, w_cls);

    dim3 grid((B + TILE - 1) / TILE, 14);
    quantum_kernel<<<grid, TILE>>>(x, B);

    final_kernel<<<(B + 255) / 256, 256>>>(w_in, b_in, scale_in, shift_in,
                                           Wc, bc, scalec, shiftc, w_out, b_out,
                                           w_cls, b_cls, out, B, Lc);
}

// round 5
// speedup vs baseline: 2.8229x; 1.6234x over previous
#include <cuda_runtime.h>
#include <math.h>

typedef unsigned long long u64;

// ---- packed f32x2 helpers (sm_103a; ptxas won't auto-fuse) ----
__device__ __forceinline__ u64 pack2(float x, float y) {
    u64 r; asm("mov.b64 %0, {%1, %2};" : "=l"(r) : "f"(x), "f"(y)); return r;
}
__device__ __forceinline__ u64 fma2(u64 a, u64 b, u64 c) {
    u64 d; asm("fma.rn.f32x2 %0, %1, %2, %3;" : "=l"(d) : "l"(a), "l"(b), "l"(c)); return d;
}
__device__ __forceinline__ u64 add2(u64 a, u64 b) {
    u64 d; asm("add.rn.f32x2 %0, %1, %2;" : "=l"(d) : "l"(a), "l"(b)); return d;
}
__device__ __forceinline__ float2 unpack2(u64 v) {
    float x, y; asm("mov.b64 {%0, %1}, %2;" : "=f"(x), "=f"(y) : "l"(v)); return make_float2(x, y);
}

#define MAXB 8192
#define TILE 128

// Folded 10x10 bilinear-form matrices, pair-packed:
// g_M2[p*50 + qp*10 + pp] = ( M̃[2qp][pp], M̃[2qp+1][pp] )   (qp=0..4, pp=0..9)
__device__ __align__(16) u64 g_M2[196 * 50];
// per-(row-group, image) partials: [0:14B) sum, [14B:28B) sumsq, [28B:42B) qdot
__device__ float g_part[3 * 14 * MAXB];

// upper-tri index -> (i,i') tables for 4-vectors
__device__ __constant__ int PI1[10] = {0,0,0,0,1,1,1,2,2,3};
__device__ __constant__ int PI2[10] = {0,1,2,3,1,2,3,2,3,3};

// ---------------------------------------------------------------------------
// Kernel 1: fold U, w_cls into per-patch A (16x16), then collapse to the
// 10x10 M̃ using psi = a01 (x) a23 tensor structure with symmetry
// multiplicities baked in. M̃[(jj')][(ii')] = Σ_sym A[4i+j][4i'+j'].
// ---------------------------------------------------------------------------
__global__ void __launch_bounds__(128) precomp_M(const float* __restrict__ U_re,
                                                 const float* __restrict__ U_im,
                                                 const float* __restrict__ w_cls)
{
    __shared__ float urs[256], uis[256];
    __shared__ float Ash[256];
    __shared__ float Msh[100];
    const int t = threadIdx.x, p = blockIdx.x;
    for (int i = t; i < 256; i += 128) { urs[i] = U_re[i]; uis[i] = U_im[i]; }
    __syncthreads();

    const float wc0 = w_cls[1 + 4 * p + 0];
    const float wc1 = w_cls[1 + 4 * p + 1];
    const float wc2 = w_cls[1 + 4 * p + 2];
    const float wc3 = w_cls[1 + 4 * p + 3];
    const float tot = wc0 + wc1 + wc2 + wc3;

    // A[r][c] = sum_k g_k (Ur[k,r]Ur[k,c] + Ui[k,r]Ui[k,c])
    for (int e = t; e < 256; e += 128) {
        const int r = e >> 4, c = e & 15;
        float acc = 0.f;
        #pragma unroll
        for (int k = 0; k < 16; k++) {
            float g = tot - 2.f * (((k & 8) ? wc0 : 0.f) + ((k & 4) ? wc1 : 0.f) +
                                   ((k & 2) ? wc2 : 0.f) + ((k & 1) ? wc3 : 0.f));
            acc += g * (urs[k * 16 + r] * urs[k * 16 + c] +
                        uis[k * 16 + r] * uis[k * 16 + c]);
        }
        Ash[e] = acc;
    }
    __syncthreads();

    if (t < 100) {
        const int qidx = t / 10, pidx = t % 10;
        const int i = PI1[pidx], i2 = PI2[pidx];
        const int j = PI1[qidx], j2 = PI2[qidx];
        float v = Ash[(4 * i + j) * 16 + 4 * i2 + j2];
        if (i != i2)            v += Ash[(4 * i2 + j) * 16 + 4 * i + j2];
        if (j != j2)            v += Ash[(4 * i + j2) * 16 + 4 * i2 + j];
        if (i != i2 && j != j2) v += Ash[(4 * i2 + j2) * 16 + 4 * i + j];
        Msh[t] = v;
    }
    __syncthreads();

    if (t < 50) {
        const int qp = t / 10, pp = t % 10;
        g_M2[p * 50 + qp * 10 + pp] = pack2(Msh[(2 * qp) * 10 + pp],
                                            Msh[(2 * qp + 1) * 10 + pp]);
    }
}

// ---------------------------------------------------------------------------
// Kernel 2: per patch, 10x10 bilinear form  C += p10^T M̃ q10  with
// q-pairs packed in the f32x2 lanes. Block = 128 images x one patch-row
// group; deterministic partial writes, no atomics.
// ---------------------------------------------------------------------------
__global__ void __launch_bounds__(TILE) quantum_kernel(const float* __restrict__ x, int B)
{
    __shared__ float xs[TILE * 57];              // 57-pad: conflict-free rows
    __shared__ __align__(16) u64 Ms[14 * 50];    // 14 M̃ matrices (5.6 KB)

    const int t  = threadIdx.x;
    const int b0 = blockIdx.x * TILE;
    const int rg = blockIdx.y;                   // 0..13

    const u64* gM = g_M2 + rg * 14 * 50;
    for (int i = t; i < 14 * 50; i += TILE) Ms[i] = gM[i];

    const int nimg = min(TILE, B - b0);
    const float* xb = x + (size_t)b0 * 784 + rg * 56;  // rows 2rg,2rg+1 contiguous
    for (int i = t; i < nimg * 56; i += TILE) {
        int img = i / 56, c = i - img * 56;
        xs[img * 57 + c] = xb[(size_t)img * 784 + c];
    }
    __syncthreads();
    if (t >= nimg) return;                       // no further block syncs

    u64 s2 = 0ull, sq2 = 0ull;                   // packed mean/sumsq partials
    float C = 0.f;
    const float* xt = xs + t * 57;

    #pragma unroll 1
    for (int pc = 0; pc < 14; pc++) {
        const float p0 = xt[2 * pc], p1 = xt[2 * pc + 1];
        const float p2 = xt[28 + 2 * pc], p3 = xt[29 + 2 * pc];
        const u64 x01 = pack2(p0, p1), x23 = pack2(p2, p3);
        s2  = add2(s2, add2(x01, x23));
        sq2 = fma2(x01, x01, fma2(x23, x23, sq2));

        float s0, c0, s1, c1, ss2, cc2, s3, c3;
        __sincosf(0.5f * p0, &s0, &c0);
        __sincosf(0.5f * p1, &s1, &c1);
        __sincosf(0.5f * p2, &ss2, &cc2);
        __sincosf(0.5f * p3, &s3, &c3);

        const float a0 = c0 * c1, a1 = c0 * s1, a2 = s0 * c1, a3 = s0 * s1;   // a01
        const float b0v = cc2 * c3, b1 = cc2 * s3, b2 = ss2 * c3, b3 = ss2 * s3; // a23

        // upper-tri outer products (multiplicities live in M̃)
        float p10[10] = {a0*a0, a0*a1, a0*a2, a0*a3, a1*a1, a1*a2, a1*a3, a2*a2, a2*a3, a3*a3};
        float q10[10] = {b0v*b0v, b0v*b1, b0v*b2, b0v*b3, b1*b1, b1*b2, b1*b3, b2*b2, b2*b3, b3*b3};

        u64 qp[5];
        #pragma unroll
        for (int qi = 0; qi < 5; qi++) qp[qi] = pack2(q10[2 * qi], q10[2 * qi + 1]);

        // acc[pp] = ( Σ_even-q M̃[q][pp] q10[q] , Σ_odd-q ... )
        u64 acc[10] = {0ull,0ull,0ull,0ull,0ull,0ull,0ull,0ull,0ull,0ull};
        const ulonglong2* M = (const ulonglong2*)(Ms + pc * 50);
        #pragma unroll
        for (int qi = 0; qi < 5; qi++) {
            #pragma unroll
            for (int h = 0; h < 5; h++) {
                ulonglong2 e = M[qi * 5 + h];     // broadcast LDS.128
                acc[2 * h]     = fma2(e.x, qp[qi], acc[2 * h]);
                acc[2 * h + 1] = fma2(e.y, qp[qi], acc[2 * h + 1]);
            }
        }
        u64 c2 = 0ull;
        #pragma unroll
        for (int pp = 0; pp < 10; pp++)
            c2 = fma2(acc[pp], pack2(p10[pp], p10[pp]), c2);
        float2 cc = unpack2(c2);
        C += cc.x + cc.y;
    }

    const float2 sv = unpack2(s2);
    const float2 qv = unpack2(sq2);
    const int b = b0 + t;
    g_part[rg * B + b]        = sv.x + sv.y;
    g_part[(14 + rg) * B + b] = qv.x + qv.y;
    g_part[(28 + rg) * B + b] = C;
}

// ---------------------------------------------------------------------------
// Kernel 3: sum partials, classical MLP, fuse, sigmoid.
// ---------------------------------------------------------------------------
__global__ void final_kernel(const float* __restrict__ w_in,  const float* __restrict__ b_in,
                             const float* __restrict__ scale_in, const float* __restrict__ shift_in,
                             const float* __restrict__ Wc,    const float* __restrict__ bc,
                             const float* __restrict__ scalec, const float* __restrict__ shiftc,
                             const float* __restrict__ w_out, const float* __restrict__ b_out,
                             const float* __restrict__ w_cls, const float* __restrict__ b_cls,
                             float* __restrict__ out, int B, int Lc)
{
    const int b = blockIdx.x * 256 + threadIdx.x;
    if (b >= B) return;
    float S = 0.f, Q = 0.f, C = 0.f;
    #pragma unroll
    for (int rg = 0; rg < 14; rg++) {
        S += g_part[rg * B + b];
        Q += g_part[(14 + rg) * B + b];
        C += g_part[(28 + rg) * B + b];
    }
    float mean = S * (1.f / 784.f);
    float var  = (Q - S * S * (1.f / 784.f)) * (1.f / 783.f);   // ddof=1
    float sd   = sqrtf(fmaxf(var, 0.f));
    float h0 = tanhf(mean * w_in[0] + sd * w_in[1] + b_in[0]) * scale_in[0] + shift_in[0];
    float h1 = tanhf(mean * w_in[2] + sd * w_in[3] + b_in[1]) * scale_in[1] + shift_in[1];
    for (int l = 0; l < Lc; l++) {
        float n0 = tanhf(h0 * Wc[l*4+0] + h1 * Wc[l*4+1] + bc[l*2+0]) * scalec[l*2+0] + shiftc[l*2+0];
        float n1 = tanhf(h0 * Wc[l*4+2] + h1 * Wc[l*4+3] + bc[l*2+1]) * scalec[l*2+1] + shiftc[l*2+1];
        h0 = n0; h1 = n1;
    }
    float cls   = h0 * w_out[0] + h1 * w_out[1] + b_out[0];
    float logit = b_cls[0] + cls * w_cls[0] + C;
    out[b] = 1.f / (1.f + __expf(-logit));
}

extern "C" void kernel_launch(void* const* d_in, const int* in_sizes, int n_in,
                              void* d_out, int out_size)
{
    const float* x        = (const float*)d_in[0];
    const float* w_in     = (const float*)d_in[1];
    const float* b_in     = (const float*)d_in[2];
    const float* scale_in = (const float*)d_in[3];
    const float* shift_in = (const float*)d_in[4];
    const float* Wc       = (const float*)d_in[5];
    const float* bc       = (const float*)d_in[6];
    const float* scalec   = (const float*)d_in[7];
    const float* shiftc   = (const float*)d_in[8];
    const float* w_out    = (const float*)d_in[9];
    const float* b_out    = (const float*)d_in[10];
    const float* U_re     = (const float*)d_in[11];
    const float* U_im     = (const float*)d_in[12];
    const float* w_cls    = (const float*)d_in[13];
    const float* b_cls    = (const float*)d_in[14];
    float* out = (float*)d_out;

    const int B  = in_sizes[0] / 784;   // (B,1,28,28)
    const int Lc = in_sizes[5] / 4;     // (L,2,2)

    precomp_M<<<196, 128>>>(U_re, U_im, w_cls);

    dim3 grid((B + TILE - 1) / TILE, 14);
    quantum_kernel<<<grid, TILE>>>(x, B);

    final_kernel<<<(B + 255) / 256, 256>>>(w_in, b_in, scale_in, shift_in,
                                           Wc, bc, scalec, shiftc, w_out, b_out,
                                           w_cls, b_cls, out, B, Lc);
}